// round 12
// baseline (speedup 1.0000x reference)
#include <cuda_runtime.h>

// Problem dims (fixed by setup_inputs)
#define Bv   1024
#define Tv   80
#define Dv   300
#define Hv   300
#define G4   1200           // 4*H
#define NTHR 256            // step kernel: 64 p-pairs x 4 j-groups (2 j each)
#define LSTM_SMEM (76800 + 30720)   // wsd (300*8*32B) + hs[2][30][128] f32

typedef unsigned long long ull;

// ---- packed f32x2 helpers (Blackwell sm_100+) ------------------------------
__device__ __forceinline__ ull pack_dup(float x) {
    ull r; unsigned u = __float_as_uint(x);
    asm("mov.b64 %0, {%1, %1};" : "=l"(r) : "r"(u));
    return r;
}
__device__ __forceinline__ void fma2(ull& d, ull a, ull b) {
    asm("fma.rn.f32x2 %0, %1, %2, %0;" : "+l"(d) : "l"(a), "l"(b));
}
__device__ __forceinline__ float2 unpack2(ull v) {
    unsigned lo, hi;
    asm("mov.b64 {%0, %1}, %2;" : "=r"(lo), "=r"(hi) : "l"(v));
    return make_float2(__uint_as_float(lo), __uint_as_float(hi));
}

// Scratch (device globals — no allocation allowed)
__device__ float g_xpre[(size_t)Tv * G4 * Bv];   // xpre[t][n][p]
__device__ float g_hT[2][Hv * Bv];               // hT[k][p], double buffered
__device__ float g_cT[Hv * Bv];                  // cT[j][p]
__device__ ull   g_wdup[Hv * Hv * 4];            // per (k,j): 4 gate-dup pairs
__device__ int   g_perm[Bv];
__device__ int   g_rank[Bv];
__device__ int   g_act[Tv];
__device__ unsigned g_bar_count;
__device__ unsigned g_bar_sense;

// ---------------------------------------------------------------------------
__global__ void init_kernel(const int* __restrict__ lens) {
    __shared__ int sl[Bv];
    const int tid = threadIdx.x;
    sl[tid] = lens[tid];
    __syncthreads();
    const int L = sl[tid];
    int r = 0;
    for (int b = 0; b < Bv; b++) {
        int L2 = sl[b];
        r += (L2 > L) || (L2 == L && b < tid);
    }
    g_rank[tid] = r;
    g_perm[r]   = tid;
    if (tid < Tv) {
        int c = 0;
        for (int b = 0; b < Bv; b++) c += (sl[b] > tid);
        g_act[tid] = c;
    }
    if (tid == 0) { g_bar_count = 0; g_bar_sense = 0; }
}

__global__ void zero_kernel() {
    int i = blockIdx.x * blockDim.x + threadIdx.x;
    if (i < Hv * Bv) {
        g_hT[0][i] = 0.f;
        g_hT[1][i] = 0.f;
        g_cT[i]    = 0.f;
    }
}

// Wh[k][g*H+j] -> g_wdup[(k*H+j)*4 + g] = (wg, wg) packed pair
__global__ void trans_kernel(const float* __restrict__ Wh) {
    int i = blockIdx.x * blockDim.x + threadIdx.x;
    if (i < Hv * Hv) {
        int k = i / Hv, j = i - k * Hv;
        const float* r = Wh + k * G4 + j;
        g_wdup[i * 4 + 0] = pack_dup(r[0]);
        g_wdup[i * 4 + 1] = pack_dup(r[Hv]);
        g_wdup[i * 4 + 2] = pack_dup(r[2 * Hv]);
        g_wdup[i * 4 + 3] = pack_dup(r[3 * Hv]);
    }
}

// ---------------------------------------------------------------------------
// Precompute xpre[t][n][p] — f32x2 packed over p-pairs (unchanged from R10).
// ---------------------------------------------------------------------------
__global__ __launch_bounds__(256, 2) void pre_kernel(
    const int*   __restrict__ sent,
    const float* __restrict__ emb,
    const float* __restrict__ Wx,
    const float* __restrict__ bias)
{
    const int t  = blockIdx.z;
    const int p0 = blockIdx.x * 128;
    const int n0 = blockIdx.y * 128;
    if (p0 >= g_act[t]) return;

    __shared__ int   idxs[128];
    __shared__ __align__(16) float es[20][128];
    __shared__ __align__(16) float ws[20][128];

    const int tid = threadIdx.x;
    const int tx  = tid & 15;
    const int ty  = tid >> 4;

    if (tid < 128) idxs[tid] = sent[g_perm[p0 + tid] * Tv + t];
    __syncthreads();

    ull acc2[8][4];                       // [ni][p-pair]
#pragma unroll
    for (int i = 0; i < 8; i++)
#pragma unroll
        for (int q = 0; q < 4; q++) acc2[i][q] = 0ull;

    for (int k0 = 0; k0 < Dv; k0 += 20) {
#pragma unroll
        for (int i = 0; i < 3; i++) {
            int idx = i * 256 + tid;
            if (idx < 640) {
                int kl = idx >> 5;
                int nq = idx & 31;
                int n  = n0 + nq * 4;
                float4 v = (n < G4) ? *(const float4*)&Wx[(k0 + kl) * G4 + n]
                                    : make_float4(0.f, 0.f, 0.f, 0.f);
                *(float4*)&ws[kl][nq * 4] = v;
            }
        }
#pragma unroll
        for (int i = 0; i < 3; i++) {
            int idx = i * 256 + tid;
            if (idx < 640) {
                int ks = idx >> 7;
                int rl = idx & 127;
                float4 v = *(const float4*)&emb[(size_t)idxs[rl] * Dv + k0 + ks * 4];
                es[ks * 4 + 0][rl] = v.x;
                es[ks * 4 + 1][rl] = v.y;
                es[ks * 4 + 2][rl] = v.z;
                es[ks * 4 + 3][rl] = v.w;
            }
        }
        __syncthreads();
#pragma unroll
        for (int k = 0; k < 20; k++) {
            ulonglong2 av0 = *(const ulonglong2*)&es[k][tx * 4];
            ulonglong2 av1 = *(const ulonglong2*)&es[k][tx * 4 + 64];
            ull ap[4] = {av0.x, av0.y, av1.x, av1.y};
            float4 w0 = *(const float4*)&ws[k][ty * 4];
            float4 w1 = *(const float4*)&ws[k][ty * 4 + 64];
            float w[8] = {w0.x, w0.y, w0.z, w0.w, w1.x, w1.y, w1.z, w1.w};
#pragma unroll
            for (int ni = 0; ni < 8; ni++) {
                ull wd = pack_dup(w[ni]);
                fma2(acc2[ni][0], wd, ap[0]);
                fma2(acc2[ni][1], wd, ap[1]);
                fma2(acc2[ni][2], wd, ap[2]);
                fma2(acc2[ni][3], wd, ap[3]);
            }
        }
        __syncthreads();
    }

#pragma unroll
    for (int ni = 0; ni < 8; ni++) {
        int n = n0 + (ni >> 2) * 64 + ty * 4 + (ni & 3);
        if (n >= G4) continue;
        float bn = bias[n];
        size_t base = ((size_t)t * G4 + n) * Bv + p0;
        float2 u0 = unpack2(acc2[ni][0]);
        float2 u1 = unpack2(acc2[ni][1]);
        float2 u2 = unpack2(acc2[ni][2]);
        float2 u3 = unpack2(acc2[ni][3]);
        float4 v0 = make_float4(u0.x + bn, u0.y + bn, u1.x + bn, u1.y + bn);
        float4 v1 = make_float4(u2.x + bn, u2.y + bn, u3.x + bn, u3.y + bn);
        __stcs((float4*)&g_xpre[base + tx * 4],      v0);
        __stcs((float4*)&g_xpre[base + tx * 4 + 64], v1);
    }
}

// ---------------------------------------------------------------------------
// Persistent LSTM recurrence. Tile = 128p x 8j x 4 gates, 256 threads.
// Thread = (p-pair, 2 j-cols): 8 fma2/k against 1 LDS.64 + 4 broadcast
// LDS.128 -> smem 40 cyc/k/SM < FMA 64 cyc/k/SM (FMA-bound).
// Gate-duplicated weights resident in smem for the whole launch.
// ---------------------------------------------------------------------------
__device__ __forceinline__ float sigmoidf_(float x) {
    return 1.f / (1.f + __expf(-x));
}
__device__ __forceinline__ float tanhf_(float x) {
    return 1.f - 2.f / (__expf(2.f * x) + 1.f);
}

__device__ __forceinline__ void grid_barrier(unsigned target, int nblk) {
    __threadfence();
    __syncthreads();
    if (threadIdx.x == 0) {
        if ((int)atomicAdd(&g_bar_count, 1u) == nblk - 1) {
            g_bar_count = 0;
            __threadfence();
            atomicExch(&g_bar_sense, target);
        } else {
            while (*(volatile unsigned*)&g_bar_sense < target) __nanosleep(32);
        }
    }
    __syncthreads();
}

__device__ __forceinline__ void step_tile(
    float hs[2][30][128], const ulonglong2* __restrict__ wsd,
    const float* __restrict__ hin, float* __restrict__ hout,
    int t, int p0, int jb, int pidx, int jc, int act)
{
    const int tid = threadIdx.x;

    float4 ph[4];
    auto load_c = [&](int k0) {
#pragma unroll
        for (int i = 0; i < 4; i++) {
            int f = i * NTHR + tid;          // 960 float4 = 30k x 128p
            if (f < 960)
                ph[i] = __ldcg((const float4*)&hin[(k0 + (f >> 5)) * Bv + p0
                                                   + ((f & 31) << 2)]);
        }
    };
    auto store_c = [&](int buf) {
#pragma unroll
        for (int i = 0; i < 4; i++) {
            int f = i * NTHR + tid;
            if (f < 960)
                *(float4*)&hs[buf][f >> 5][(f & 31) << 2] = ph[i];
        }
    };

    ull accA[4], accB[4];
#pragma unroll
    for (int g = 0; g < 4; g++) { accA[g] = 0ull; accB[g] = 0ull; }

    load_c(0);
    store_c(0);
    __syncthreads();

#pragma unroll 1
    for (int c = 0; c < 10; c++) {
        const int cur = c & 1;
        if (c < 9) load_c((c + 1) * 30);
#pragma unroll
        for (int kk = 0; kk < 30; kk++) {
            const int k = c * 30 + kk;
            ull hp = *(const ull*)&hs[cur][kk][pidx * 2];
            const ulonglong2* wrow = &wsd[(k * 8 + jc * 2) * 2];
            ulonglong2 wa01 = wrow[0];
            ulonglong2 wa23 = wrow[1];
            ulonglong2 wb01 = wrow[2];
            ulonglong2 wb23 = wrow[3];
            fma2(accA[0], hp, wa01.x);
            fma2(accA[1], hp, wa01.y);
            fma2(accA[2], hp, wa23.x);
            fma2(accA[3], hp, wa23.y);
            fma2(accB[0], hp, wb01.x);
            fma2(accB[1], hp, wb01.y);
            fma2(accB[2], hp, wb23.x);
            fma2(accB[3], hp, wb23.y);
        }
        if (c < 9) { store_c(cur ^ 1); __syncthreads(); }
    }

    const size_t tb = (size_t)t * G4;
    const int pb = p0 + pidx * 2;

#pragma unroll
    for (int jj = 0; jj < 2; jj++) {
        const int j = jb + jj;
        if (j >= Hv) continue;
        const ull* acc = jj ? accB : accA;
        const int hi = j * Bv + pb;

        if (pb + 2 <= act) {                 // fully active: float2 path
            float2 xi = __ldcs((const float2*)&g_xpre[(tb + 0 * Hv + j) * Bv + pb]);
            float2 xf = __ldcs((const float2*)&g_xpre[(tb + 1 * Hv + j) * Bv + pb]);
            float2 xg = __ldcs((const float2*)&g_xpre[(tb + 2 * Hv + j) * Bv + pb]);
            float2 xo = __ldcs((const float2*)&g_xpre[(tb + 3 * Hv + j) * Bv + pb]);
            float2 c2 = __ldcg((const float2*)&g_cT[hi]);
            float2 gi = unpack2(acc[0]);
            float2 gf = unpack2(acc[1]);
            float2 gg = unpack2(acc[2]);
            float2 go = unpack2(acc[3]);

            float iv0 = sigmoidf_(gi.x + xi.x), iv1 = sigmoidf_(gi.y + xi.y);
            float fv0 = sigmoidf_(gf.x + xf.x), fv1 = sigmoidf_(gf.y + xf.y);
            float gv0 = tanhf_   (gg.x + xg.x), gv1 = tanhf_   (gg.y + xg.y);
            float ov0 = sigmoidf_(go.x + xo.x), ov1 = sigmoidf_(go.y + xo.y);
            float cn0 = fv0 * c2.x + iv0 * gv0;
            float cn1 = fv1 * c2.y + iv1 * gv1;
            float hn0 = ov0 * tanhf_(cn0);
            float hn1 = ov1 * tanhf_(cn1);
            __stcg((float2*)&hout[hi], make_float2(hn0, hn1));
            __stcg((float2*)&g_cT[hi], make_float2(cn0, cn1));
        } else {                              // straddle: masked scalar
            float2 gi = unpack2(acc[0]);
            float2 gf = unpack2(acc[1]);
            float2 gg = unpack2(acc[2]);
            float2 go = unpack2(acc[3]);
            float giv[2] = {gi.x, gi.y}, gfv[2] = {gf.x, gf.y};
            float ggv[2] = {gg.x, gg.y}, gov[2] = {go.x, go.y};
#pragma unroll
            for (int p = 0; p < 2; p++) {
                const int pp = pb + p;
                if (pp >= act) continue;
                float ga = giv[p] + __ldcs(&g_xpre[(tb + 0 * Hv + j) * Bv + pp]);
                float gb = gfv[p] + __ldcs(&g_xpre[(tb + 1 * Hv + j) * Bv + pp]);
                float gc = ggv[p] + __ldcs(&g_xpre[(tb + 2 * Hv + j) * Bv + pp]);
                float gd = gov[p] + __ldcs(&g_xpre[(tb + 3 * Hv + j) * Bv + pp]);
                float iv = sigmoidf_(ga);
                float fv = sigmoidf_(gb);
                float gv = tanhf_(gc);
                float ov = sigmoidf_(gd);
                float cold = __ldcg(&g_cT[hi + p]);
                float cnew = fv * cold + iv * gv;
                float hnew = ov * tanhf_(cnew);
                __stcg(&g_cT[hi + p], cnew);
                __stcg(&hout[hi + p], hnew);
            }
        }
    }
}

__global__ __launch_bounds__(NTHR, 2) void lstm_kernel(int nblk)
{
    extern __shared__ __align__(16) char smem_raw[];
    ulonglong2* wsd = (ulonglong2*)smem_raw;                        // 76800 B
    float (*hs)[30][128] = (float(*)[30][128])(smem_raw + 76800);   // 30720 B

    const int bid  = blockIdx.x;
    const int tid  = threadIdx.x;
    const int jt   = bid % 38;               // fixed j-tile (Wh residency)
    const int pslt = bid / 38;               // p-slot
    const int j0   = jt * 8;
    const int pidx = tid & 63;               // p-pair 0..63
    const int jc   = tid >> 6;               // 0..3 (2 j-cols each)
    const int jb   = j0 + jc * 2;
    // blocks sharing this jt (exact coverage for any nblk)
    const int nbj  = (nblk - 1 - jt) / 38 + 1;

    // load gate-duplicated Wh slice once (resident whole launch)
    for (int i = tid; i < 4800; i += NTHR) {
        int half = i & 1;
        int jl   = (i >> 1) & 7;
        int k    = i >> 4;
        int col  = j0 + jl;
        ulonglong2 v = make_ulonglong2(0ull, 0ull);
        if (col < Hv)
            v = ((const ulonglong2*)g_wdup)[(k * Hv + col) * 2 + half];
        wsd[i] = v;
    }
    __syncthreads();

#pragma unroll 1
    for (int t = 0; t < Tv; t++) {
        const int act = g_act[t];
        const int np  = (act + 127) >> 7;
        const float* hin  = g_hT[t & 1];
        float*       hout = g_hT[(t & 1) ^ 1];

        for (int pt = pslt; pt < np; pt += nbj)
            step_tile(hs, wsd, hin, hout, t, pt * 128, jb, pidx, jc, act);

        grid_barrier(t + 1, nblk);
    }
}

// ---------------------------------------------------------------------------
// Output: final h for batch b lives in buffer lens[b] & 1 (written at len-1).
// ---------------------------------------------------------------------------
__global__ void out_kernel(const int* __restrict__ lens,
                           const float* __restrict__ Wout,
                           const float* __restrict__ bout,
                           float* __restrict__ out)
{
    int gwarp = (blockIdx.x * blockDim.x + threadIdx.x) >> 5;
    int lane  = threadIdx.x & 31;
    if (gwarp >= Bv) return;

    const int p = g_rank[gwarp];
    const float* hbuf = g_hT[lens[gwarp] & 1];
    float s0 = 0.f, s1 = 0.f, s2 = 0.f;
    for (int jj = lane; jj < Hv; jj += 32) {
        float hv = hbuf[jj * Bv + p];
        s0 = fmaf(hv, Wout[jj * 3 + 0], s0);
        s1 = fmaf(hv, Wout[jj * 3 + 1], s1);
        s2 = fmaf(hv, Wout[jj * 3 + 2], s2);
    }
#pragma unroll
    for (int off = 16; off > 0; off >>= 1) {
        s0 += __shfl_down_sync(0xffffffffu, s0, off);
        s1 += __shfl_down_sync(0xffffffffu, s1, off);
        s2 += __shfl_down_sync(0xffffffffu, s2, off);
    }
    if (lane == 0) {
        out[gwarp * 3 + 0] = s0 + bout[0];
        out[gwarp * 3 + 1] = s1 + bout[1];
        out[gwarp * 3 + 2] = s2 + bout[2];
    }
}

// ---------------------------------------------------------------------------
extern "C" void kernel_launch(void* const* d_in, const int* in_sizes, int n_in,
                              void* d_out, int out_size)
{
    const int*   sent = (const int*)  d_in[0];
    const int*   lens = (const int*)  d_in[1];
    const float* emb  = (const float*)d_in[2];
    const float* Wx   = (const float*)d_in[3];
    const float* Wh   = (const float*)d_in[4];
    const float* bias = (const float*)d_in[5];
    const float* Wout = (const float*)d_in[6];
    const float* bout = (const float*)d_in[7];
    float* out = (float*)d_out;

    // persistent grid sized to the actual chip (148 or 152 SMs), capped at
    // the max tile count (8 p-tiles x 38 j-tiles). Attribute query is
    // host-side only — graph-capture safe.
    int dev = 0, sms = 148;
    cudaGetDevice(&dev);
    cudaDeviceGetAttribute(&sms, cudaDevAttrMultiProcessorCount, dev);
    int nblk = 2 * sms;
    if (nblk > 304) nblk = 304;

    cudaFuncSetAttribute(lstm_kernel,
                         cudaFuncAttributeMaxDynamicSharedMemorySize, LSTM_SMEM);

    init_kernel<<<1, 1024>>>(lens);
    zero_kernel<<<(Hv * Bv + 255) / 256, 256>>>();
    trans_kernel<<<(Hv * Hv + 255) / 256, 256>>>(Wh);

    dim3 pg(Bv / 128, (G4 + 127) / 128, Tv);   // 8 x 10 x 80
    pre_kernel<<<pg, 256>>>(sent, emb, Wx, bias);

    // one persistent launch for all 80 timesteps
    lstm_kernel<<<nblk, NTHR, LSTM_SMEM>>>(nblk);

    out_kernel<<<(Bv * 32 + 127) / 128, 128>>>(lens, Wout, bout, out);
}

// round 13
// speedup vs baseline: 1.3499x; 1.3499x over previous
#include <cuda_runtime.h>

// Problem dims (fixed by setup_inputs)
#define Bv   1024
#define Tv   80
#define Dv   300
#define Hv   300
#define G4   1200           // 4*H
#define NBLK 285            // 19 j-tiles x 15 p-strides; 2/SM resident (90KB smem)
#define NTHR 512
#define LSTM_SMEM (76800 + 15360)   // ws4 (300*16 float4) + hs (2*30*64 f32)

typedef unsigned long long ull;

// ---- packed f32x2 helpers (Blackwell sm_100+) ------------------------------
__device__ __forceinline__ ull pack_dup(float x) {
    ull r; unsigned u = __float_as_uint(x);
    asm("mov.b64 %0, {%1, %1};" : "=l"(r) : "r"(u));
    return r;
}
__device__ __forceinline__ void fma2(ull& d, ull a, ull b) {
    asm("fma.rn.f32x2 %0, %1, %2, %0;" : "+l"(d) : "l"(a), "l"(b));
}
__device__ __forceinline__ float2 unpack2(ull v) {
    unsigned lo, hi;
    asm("mov.b64 {%0, %1}, %2;" : "=r"(lo), "=r"(hi) : "l"(v));
    return make_float2(__uint_as_float(lo), __uint_as_float(hi));
}

// Scratch (device globals — no allocation allowed)
__device__ float g_xpre[(size_t)Tv * G4 * Bv];   // xpre[t][n][p]
__device__ float g_hT[2][Hv * Bv];               // hT[k][p], double buffered
__device__ float g_cT[Hv * Bv];                  // cT[j][p]
__device__ float4 g_whT[Hv * Hv];                // whT[k*H+j] = 4 gate weights
__device__ int   g_perm[Bv];
__device__ int   g_rank[Bv];
__device__ int   g_act[Tv];
__device__ unsigned g_bar_count;
__device__ unsigned g_bar_sense;

// ---------------------------------------------------------------------------
__global__ void init_kernel(const int* __restrict__ lens) {
    __shared__ int sl[Bv];
    const int tid = threadIdx.x;
    sl[tid] = lens[tid];
    __syncthreads();
    const int L = sl[tid];
    int r = 0;
    for (int b = 0; b < Bv; b++) {
        int L2 = sl[b];
        r += (L2 > L) || (L2 == L && b < tid);
    }
    g_rank[tid] = r;
    g_perm[r]   = tid;
    if (tid < Tv) {
        int c = 0;
        for (int b = 0; b < Bv; b++) c += (sl[b] > tid);
        g_act[tid] = c;
    }
    if (tid == 0) { g_bar_count = 0; g_bar_sense = 0; }
}

__global__ void zero_kernel() {
    int i = blockIdx.x * blockDim.x + threadIdx.x;
    if (i < Hv * Bv) {
        g_hT[0][i] = 0.f;
        g_hT[1][i] = 0.f;
        g_cT[i]    = 0.f;
    }
}

// Transpose Wh[k][g*H+j] -> whT[k*H+j] = float4(g0,g1,g2,g3)
__global__ void trans_kernel(const float* __restrict__ Wh) {
    int i = blockIdx.x * blockDim.x + threadIdx.x;
    if (i < Hv * Hv) {
        int k = i / Hv, j = i - k * Hv;
        const float* r = Wh + k * G4 + j;
        g_whT[i] = make_float4(r[0], r[Hv], r[2 * Hv], r[3 * Hv]);
    }
}

// ---------------------------------------------------------------------------
// Precompute xpre[t][n][p] — f32x2 packed over p-pairs.
// Double-buffered smem staging: register prefetch of chunk c+1 during
// compute of chunk c, ONE __syncthreads per chunk (was two).
// ---------------------------------------------------------------------------
__global__ __launch_bounds__(256, 2) void pre_kernel(
    const int*   __restrict__ sent,
    const float* __restrict__ emb,
    const float* __restrict__ Wx,
    const float* __restrict__ bias)
{
    const int t  = blockIdx.z;
    const int p0 = blockIdx.x * 128;
    const int n0 = blockIdx.y * 128;
    if (p0 >= g_act[t]) return;

    __shared__ int   idxs[128];
    __shared__ __align__(16) float es[2][20][128];
    __shared__ __align__(16) float ws[2][20][128];

    const int tid = threadIdx.x;
    const int tx  = tid & 15;
    const int ty  = tid >> 4;

    if (tid < 128) idxs[tid] = sent[g_perm[p0 + tid] * Tv + t];
    __syncthreads();

    ull acc2[8][4];                       // [ni][p-pair]
#pragma unroll
    for (int i = 0; i < 8; i++)
#pragma unroll
        for (int q = 0; q < 4; q++) acc2[i][q] = 0ull;

    // register prefetch buffers: 640 float4 each / 256 threads -> 3 slots
    float4 pw[3], pe[3];

    auto load_c = [&](int k0) {
#pragma unroll
        for (int i = 0; i < 3; i++) {
            int idx = i * 256 + tid;
            if (idx < 640) {
                int kl = idx >> 5;
                int nq = idx & 31;
                int n  = n0 + nq * 4;
                pw[i] = (n < G4) ? *(const float4*)&Wx[(k0 + kl) * G4 + n]
                                 : make_float4(0.f, 0.f, 0.f, 0.f);
            }
        }
#pragma unroll
        for (int i = 0; i < 3; i++) {
            int idx = i * 256 + tid;
            if (idx < 640) {
                int ks = idx >> 7;          // 0..4 (warp-uniform)
                int rl = idx & 127;
                pe[i] = *(const float4*)&emb[(size_t)idxs[rl] * Dv + k0 + ks * 4];
            }
        }
    };
    auto store_c = [&](int buf) {
#pragma unroll
        for (int i = 0; i < 3; i++) {
            int idx = i * 256 + tid;
            if (idx < 640) {
                int kl = idx >> 5;
                int nq = idx & 31;
                *(float4*)&ws[buf][kl][nq * 4] = pw[i];
            }
        }
#pragma unroll
        for (int i = 0; i < 3; i++) {
            int idx = i * 256 + tid;
            if (idx < 640) {
                int ks = idx >> 7;
                int rl = idx & 127;
                es[buf][ks * 4 + 0][rl] = pe[i].x;
                es[buf][ks * 4 + 1][rl] = pe[i].y;
                es[buf][ks * 4 + 2][rl] = pe[i].z;
                es[buf][ks * 4 + 3][rl] = pe[i].w;
            }
        }
    };

    load_c(0);
    store_c(0);
    __syncthreads();

#pragma unroll 1
    for (int c = 0; c < 15; c++) {
        const int cur = c & 1;
        if (c < 14) load_c((c + 1) * 20);
#pragma unroll
        for (int k = 0; k < 20; k++) {
            ulonglong2 av0 = *(const ulonglong2*)&es[cur][k][tx * 4];
            ulonglong2 av1 = *(const ulonglong2*)&es[cur][k][tx * 4 + 64];
            ull ap[4] = {av0.x, av0.y, av1.x, av1.y};
            float4 w0 = *(const float4*)&ws[cur][k][ty * 4];
            float4 w1 = *(const float4*)&ws[cur][k][ty * 4 + 64];
            float w[8] = {w0.x, w0.y, w0.z, w0.w, w1.x, w1.y, w1.z, w1.w};
#pragma unroll
            for (int ni = 0; ni < 8; ni++) {
                ull wd = pack_dup(w[ni]);
                fma2(acc2[ni][0], wd, ap[0]);
                fma2(acc2[ni][1], wd, ap[1]);
                fma2(acc2[ni][2], wd, ap[2]);
                fma2(acc2[ni][3], wd, ap[3]);
            }
        }
        if (c < 14) { store_c(cur ^ 1); __syncthreads(); }
    }

#pragma unroll
    for (int ni = 0; ni < 8; ni++) {
        int n = n0 + (ni >> 2) * 64 + ty * 4 + (ni & 3);
        if (n >= G4) continue;
        float bn = bias[n];
        size_t base = ((size_t)t * G4 + n) * Bv + p0;
        float2 u0 = unpack2(acc2[ni][0]);
        float2 u1 = unpack2(acc2[ni][1]);
        float2 u2 = unpack2(acc2[ni][2]);
        float2 u3 = unpack2(acc2[ni][3]);
        float4 v0 = make_float4(u0.x + bn, u0.y + bn, u1.x + bn, u1.y + bn);
        float4 v1 = make_float4(u2.x + bn, u2.y + bn, u3.x + bn, u3.y + bn);
        __stcs((float4*)&g_xpre[base + tx * 4],      v0);
        __stcs((float4*)&g_xpre[base + tx * 4 + 64], v1);
    }
}

// ---------------------------------------------------------------------------
// Persistent LSTM recurrence (R10 configuration — best measured: 2404 us).
// Wh phase-resident, 512 thr, W=16/8 j-tiles, f32x2 gate-pair packing.
// ---------------------------------------------------------------------------
__device__ __forceinline__ float sigmoidf_(float x) {
    return 1.f / (1.f + __expf(-x));
}
__device__ __forceinline__ float tanhf_(float x) {
    return 1.f - 2.f / (__expf(2.f * x) + 1.f);
}

__device__ __forceinline__ void grid_barrier(unsigned target) {
    __threadfence();
    __syncthreads();
    if (threadIdx.x == 0) {
        if (atomicAdd(&g_bar_count, 1u) == NBLK - 1) {
            g_bar_count = 0;
            __threadfence();
            atomicExch(&g_bar_sense, target);
        } else {
            while (*(volatile unsigned*)&g_bar_sense < target) __nanosleep(32);
        }
    }
    __syncthreads();
}

// One tile: 64 p x W j-cols x 4 gates, 512 threads (W=16: PPT=2; W=8: PPT=1).
template<int W>
__device__ __forceinline__ void step_tile_full(
    float hs[2][30][64], const float4* __restrict__ ws4,
    const float* __restrict__ hin, float* __restrict__ hout,
    int t, int p0, int j0, int act)
{
    constexpr int TPJ = NTHR / W;        // 32 or 64
    constexpr int PPT = 64 / TPJ;        // 2 or 1
    const int tid  = threadIdx.x;
    const int pidx = tid % TPJ;
    const int jc   = tid / TPJ;
    const int j    = j0 + jc;
    const bool ldon = tid < 480;         // 480 float4 = 30k x 64p per chunk

    float4 ph;
    auto load_c = [&](int k0) {
        if (ldon)
            ph = __ldcg((const float4*)&hin[(k0 + (tid >> 4)) * Bv + p0
                                            + ((tid & 15) << 2)]);
    };
    auto store_c = [&](int buf) {
        if (ldon)
            *(float4*)&hs[buf][tid >> 4][(tid & 15) << 2] = ph;
    };

    // packed accumulators: acc01 = (gate0, gate1), acc23 = (gate2, gate3)
    ull acc01[PPT], acc23[PPT];
#pragma unroll
    for (int p = 0; p < PPT; p++) { acc01[p] = 0ull; acc23[p] = 0ull; }

    load_c(0);
    store_c(0);
    __syncthreads();

#pragma unroll 1
    for (int c = 0; c < 10; c++) {
        const int cur = c & 1;
        if (c < 9) load_c((c + 1) * 30);
#pragma unroll
        for (int kk = 0; kk < 30; kk++) {
            const int k = c * 30 + kk;
            ulonglong2 wv = *(const ulonglong2*)&ws4[k * W + jc]; // (g0g1),(g2g3)
            if (PPT == 2) {
                float2 h2 = *(const float2*)&hs[cur][kk][pidx * 2];
                ull hh0 = pack_dup(h2.x);
                ull hh1 = pack_dup(h2.y);
                fma2(acc01[0], hh0, wv.x);
                fma2(acc23[0], hh0, wv.y);
                fma2(acc01[1], hh1, wv.x);
                fma2(acc23[1], hh1, wv.y);
            } else {
                ull hh = pack_dup(hs[cur][kk][pidx]);
                fma2(acc01[0], hh, wv.x);
                fma2(acc23[0], hh, wv.y);
            }
        }
        if (c < 9) { store_c(cur ^ 1); __syncthreads(); }
    }

    if (j < Hv) {
        const size_t tb = (size_t)t * G4;
        const int pb = p0 + pidx * PPT;
        const int hi = j * Bv + pb;

        if (PPT == 2 && pb + 2 <= act) {   // fully active: float2 path
            float xp[4][2];
#pragma unroll
            for (int g = 0; g < 4; g++) {
                float2 v = __ldcs((const float2*)&g_xpre[(tb + g * Hv + j) * Bv + pb]);
                xp[g][0] = v.x; xp[g][1] = v.y;
            }
            float2 c2 = __ldcg((const float2*)&g_cT[hi]);
            float cold[2] = {c2.x, c2.y};
            float hn[2], cn[2];
#pragma unroll
            for (int p = 0; p < 2; p++) {
                float2 g01 = unpack2(acc01[p]);
                float2 g23 = unpack2(acc23[p]);
                float iv = sigmoidf_(g01.x + xp[0][p]);
                float fv = sigmoidf_(g01.y + xp[1][p]);
                float gv = tanhf_   (g23.x + xp[2][p]);
                float ov = sigmoidf_(g23.y + xp[3][p]);
                cn[p] = fv * cold[p] + iv * gv;
                hn[p] = ov * tanhf_(cn[p]);
            }
            __stcg((float2*)&hout[hi], make_float2(hn[0], hn[1]));
            __stcg((float2*)&g_cT[hi], make_float2(cn[0], cn[1]));
        } else {                            // straddle / narrow: masked scalar
#pragma unroll
            for (int p = 0; p < PPT; p++) {
                const int pp = pb + p;
                if (pp >= act) continue;
                float2 g01 = unpack2(acc01[p]);
                float2 g23 = unpack2(acc23[p]);
                float gi = g01.x + __ldcs(&g_xpre[(tb + 0 * Hv + j) * Bv + pp]);
                float gf = g01.y + __ldcs(&g_xpre[(tb + 1 * Hv + j) * Bv + pp]);
                float gg = g23.x + __ldcs(&g_xpre[(tb + 2 * Hv + j) * Bv + pp]);
                float go = g23.y + __ldcs(&g_xpre[(tb + 3 * Hv + j) * Bv + pp]);
                float iv = sigmoidf_(gi);
                float fv = sigmoidf_(gf);
                float gv = tanhf_(gg);
                float ov = sigmoidf_(go);
                float cold = __ldcg(&g_cT[hi + p]);
                float cnew = fv * cold + iv * gv;
                float hnew = ov * tanhf_(cnew);
                __stcg(&g_cT[hi + p], cnew);
                __stcg(&hout[hi + p], hnew);
            }
        }
    }
    __syncthreads();   // protect hs before next tile reuses it
}

__global__ __launch_bounds__(NTHR, 2) void lstm_kernel()
{
    extern __shared__ __align__(16) char smem_raw[];
    float4* ws4 = (float4*)smem_raw;                            // 76800 B
    float (*hs)[30][64] = (float(*)[30][64])(smem_raw + 76800); // 15360 B

    const int bid = blockIdx.x;
    const int tid = threadIdx.x;
    int wlast = 0;

#pragma unroll 1
    for (int t = 0; t < Tv; t++) {
        const int act = g_act[t];
        const int na  = (act + 63) >> 6;
        const float* hin  = g_hT[t & 1];
        float*       hout = g_hT[(t & 1) ^ 1];

        int w, njt, lw;
        if (na >= 8) { w = 16; njt = 19; lw = 4; }
        else         { w = 8;  njt = 38; lw = 3; }
        const int jt  = bid % njt;
        const int ptb = bid / njt;
        const int j0  = jt * w;

        if (w != wlast) {    // phase change (happens once): load Wh slice
            for (int idx = tid; idx < 300 * w; idx += NTHR) {
                int k   = idx >> lw;
                int jj  = idx & (w - 1);
                int col = j0 + jj;
                ws4[idx] = (col < Hv) ? g_whT[k * Hv + col]
                                      : make_float4(0.f, 0.f, 0.f, 0.f);
            }
            wlast = w;
            __syncthreads();
        }

        int stride;
        if (w == 16) stride = 15;                   // 285 = 19*15 exact
        else         stride = (jt < 19) ? 8 : 7;    // 285 = 7*38 + 19

        if (w == 16) {
            for (int pp = ptb; pp * 64 < act; pp += stride)
                step_tile_full<16>(hs, ws4, hin, hout, t, pp * 64, j0, act);
        } else {
            for (int pp = ptb; pp * 64 < act; pp += stride)
                step_tile_full<8>(hs, ws4, hin, hout, t, pp * 64, j0, act);
        }
        grid_barrier(t + 1);
    }
}

// ---------------------------------------------------------------------------
// Output: final h for batch b lives in buffer lens[b] & 1 (written at len-1).
// ---------------------------------------------------------------------------
__global__ void out_kernel(const int* __restrict__ lens,
                           const float* __restrict__ Wout,
                           const float* __restrict__ bout,
                           float* __restrict__ out)
{
    int gwarp = (blockIdx.x * blockDim.x + threadIdx.x) >> 5;
    int lane  = threadIdx.x & 31;
    if (gwarp >= Bv) return;

    const int p = g_rank[gwarp];
    const float* hbuf = g_hT[lens[gwarp] & 1];
    float s0 = 0.f, s1 = 0.f, s2 = 0.f;
    for (int jj = lane; jj < Hv; jj += 32) {
        float hv = hbuf[jj * Bv + p];
        s0 = fmaf(hv, Wout[jj * 3 + 0], s0);
        s1 = fmaf(hv, Wout[jj * 3 + 1], s1);
        s2 = fmaf(hv, Wout[jj * 3 + 2], s2);
    }
#pragma unroll
    for (int off = 16; off > 0; off >>= 1) {
        s0 += __shfl_down_sync(0xffffffffu, s0, off);
        s1 += __shfl_down_sync(0xffffffffu, s1, off);
        s2 += __shfl_down_sync(0xffffffffu, s2, off);
    }
    if (lane == 0) {
        out[gwarp * 3 + 0] = s0 + bout[0];
        out[gwarp * 3 + 1] = s1 + bout[1];
        out[gwarp * 3 + 2] = s2 + bout[2];
    }
}

// ---------------------------------------------------------------------------
extern "C" void kernel_launch(void* const* d_in, const int* in_sizes, int n_in,
                              void* d_out, int out_size)
{
    const int*   sent = (const int*)  d_in[0];
    const int*   lens = (const int*)  d_in[1];
    const float* emb  = (const float*)d_in[2];
    const float* Wx   = (const float*)d_in[3];
    const float* Wh   = (const float*)d_in[4];
    const float* bias = (const float*)d_in[5];
    const float* Wout = (const float*)d_in[6];
    const float* bout = (const float*)d_in[7];
    float* out = (float*)d_out;

    cudaFuncSetAttribute(lstm_kernel,
                         cudaFuncAttributeMaxDynamicSharedMemorySize, LSTM_SMEM);

    init_kernel<<<1, 1024>>>(lens);
    zero_kernel<<<(Hv * Bv + 255) / 256, 256>>>();
    trans_kernel<<<(Hv * Hv + 255) / 256, 256>>>(Wh);

    dim3 pg(Bv / 128, (G4 + 127) / 128, Tv);   // 8 x 10 x 80
    pre_kernel<<<pg, 256>>>(sent, emb, Wx, bias);

    // one persistent launch for all 80 timesteps
    lstm_kernel<<<NBLK, NTHR, LSTM_SMEM>>>();

    out_kernel<<<(Bv * 32 + 127) / 128, 128>>>(lens, Wout, bout, out);
}

// round 14
// speedup vs baseline: 1.4269x; 1.0570x over previous
#include <cuda_runtime.h>

// Problem dims (fixed by setup_inputs)
#define Bv   1024
#define Tv   80
#define Dv   300
#define Hv   300
#define G4   1200           // 4*H
#define NBLK 285            // 19 j-tiles x 15 p-strides; 2/SM resident
#define NTHR 256
#define LSTM_SMEM (76800 + 15360)   // ws4 (300*16 float4) + hs (2*30*64 f32)

typedef unsigned long long ull;

// ---- packed f32x2 helpers (Blackwell sm_100+) ------------------------------
__device__ __forceinline__ ull pack_dup(float x) {
    ull r; unsigned u = __float_as_uint(x);
    asm("mov.b64 %0, {%1, %1};" : "=l"(r) : "r"(u));
    return r;
}
__device__ __forceinline__ void fma2(ull& d, ull a, ull b) {
    asm("fma.rn.f32x2 %0, %1, %2, %0;" : "+l"(d) : "l"(a), "l"(b));
}
__device__ __forceinline__ float2 unpack2(ull v) {
    unsigned lo, hi;
    asm("mov.b64 {%0, %1}, %2;" : "=r"(lo), "=r"(hi) : "l"(v));
    return make_float2(__uint_as_float(lo), __uint_as_float(hi));
}

// Scratch (device globals — no allocation allowed)
__device__ float g_xpre[(size_t)Tv * G4 * Bv];   // xpre[t][n][p]
__device__ float g_hT[2][Hv * Bv];               // hT[k][p], double buffered
__device__ float g_cT[Hv * Bv];                  // cT[j][p]
__device__ float4 g_whT[Hv * Hv];                // whT[k*H+j] = 4 gate weights
__device__ int   g_perm[Bv];
__device__ int   g_rank[Bv];
__device__ int   g_act[Tv];
__device__ unsigned g_bar_count;
__device__ unsigned g_bar_sense;

// ---------------------------------------------------------------------------
__global__ void init_kernel(const int* __restrict__ lens) {
    __shared__ int sl[Bv];
    const int tid = threadIdx.x;
    sl[tid] = lens[tid];
    __syncthreads();
    const int L = sl[tid];
    int r = 0;
    for (int b = 0; b < Bv; b++) {
        int L2 = sl[b];
        r += (L2 > L) || (L2 == L && b < tid);
    }
    g_rank[tid] = r;
    g_perm[r]   = tid;
    if (tid < Tv) {
        int c = 0;
        for (int b = 0; b < Bv; b++) c += (sl[b] > tid);
        g_act[tid] = c;
    }
    if (tid == 0) { g_bar_count = 0; g_bar_sense = 0; }
}

__global__ void zero_kernel() {
    int i = blockIdx.x * blockDim.x + threadIdx.x;
    if (i < Hv * Bv) {
        g_hT[0][i] = 0.f;
        g_hT[1][i] = 0.f;
        g_cT[i]    = 0.f;
    }
}

// Transpose Wh[k][g*H+j] -> whT[k*H+j] = float4(g0,g1,g2,g3)
__global__ void trans_kernel(const float* __restrict__ Wh) {
    int i = blockIdx.x * blockDim.x + threadIdx.x;
    if (i < Hv * Hv) {
        int k = i / Hv, j = i - k * Hv;
        const float* r = Wh + k * G4 + j;
        g_whT[i] = make_float4(r[0], r[Hv], r[2 * Hv], r[3 * Hv]);
    }
}

// ---------------------------------------------------------------------------
// Precompute xpre[t][n][p] — f32x2 packed over p-pairs, double-buffered
// staging with register prefetch, one sync per chunk. (R13 — unchanged)
// ---------------------------------------------------------------------------
__global__ __launch_bounds__(256, 2) void pre_kernel(
    const int*   __restrict__ sent,
    const float* __restrict__ emb,
    const float* __restrict__ Wx,
    const float* __restrict__ bias)
{
    const int t  = blockIdx.z;
    const int p0 = blockIdx.x * 128;
    const int n0 = blockIdx.y * 128;
    if (p0 >= g_act[t]) return;

    __shared__ int   idxs[128];
    __shared__ __align__(16) float es[2][20][128];
    __shared__ __align__(16) float ws[2][20][128];

    const int tid = threadIdx.x;
    const int tx  = tid & 15;
    const int ty  = tid >> 4;

    if (tid < 128) idxs[tid] = sent[g_perm[p0 + tid] * Tv + t];
    __syncthreads();

    ull acc2[8][4];                       // [ni][p-pair]
#pragma unroll
    for (int i = 0; i < 8; i++)
#pragma unroll
        for (int q = 0; q < 4; q++) acc2[i][q] = 0ull;

    float4 pw[3], pe[3];

    auto load_c = [&](int k0) {
#pragma unroll
        for (int i = 0; i < 3; i++) {
            int idx = i * 256 + tid;
            if (idx < 640) {
                int kl = idx >> 5;
                int nq = idx & 31;
                int n  = n0 + nq * 4;
                pw[i] = (n < G4) ? *(const float4*)&Wx[(k0 + kl) * G4 + n]
                                 : make_float4(0.f, 0.f, 0.f, 0.f);
            }
        }
#pragma unroll
        for (int i = 0; i < 3; i++) {
            int idx = i * 256 + tid;
            if (idx < 640) {
                int ks = idx >> 7;
                int rl = idx & 127;
                pe[i] = *(const float4*)&emb[(size_t)idxs[rl] * Dv + k0 + ks * 4];
            }
        }
    };
    auto store_c = [&](int buf) {
#pragma unroll
        for (int i = 0; i < 3; i++) {
            int idx = i * 256 + tid;
            if (idx < 640) {
                int kl = idx >> 5;
                int nq = idx & 31;
                *(float4*)&ws[buf][kl][nq * 4] = pw[i];
            }
        }
#pragma unroll
        for (int i = 0; i < 3; i++) {
            int idx = i * 256 + tid;
            if (idx < 640) {
                int ks = idx >> 7;
                int rl = idx & 127;
                es[buf][ks * 4 + 0][rl] = pe[i].x;
                es[buf][ks * 4 + 1][rl] = pe[i].y;
                es[buf][ks * 4 + 2][rl] = pe[i].z;
                es[buf][ks * 4 + 3][rl] = pe[i].w;
            }
        }
    };

    load_c(0);
    store_c(0);
    __syncthreads();

#pragma unroll 1
    for (int c = 0; c < 15; c++) {
        const int cur = c & 1;
        if (c < 14) load_c((c + 1) * 20);
#pragma unroll
        for (int k = 0; k < 20; k++) {
            ulonglong2 av0 = *(const ulonglong2*)&es[cur][k][tx * 4];
            ulonglong2 av1 = *(const ulonglong2*)&es[cur][k][tx * 4 + 64];
            ull ap[4] = {av0.x, av0.y, av1.x, av1.y};
            float4 w0 = *(const float4*)&ws[cur][k][ty * 4];
            float4 w1 = *(const float4*)&ws[cur][k][ty * 4 + 64];
            float w[8] = {w0.x, w0.y, w0.z, w0.w, w1.x, w1.y, w1.z, w1.w};
#pragma unroll
            for (int ni = 0; ni < 8; ni++) {
                ull wd = pack_dup(w[ni]);
                fma2(acc2[ni][0], wd, ap[0]);
                fma2(acc2[ni][1], wd, ap[1]);
                fma2(acc2[ni][2], wd, ap[2]);
                fma2(acc2[ni][3], wd, ap[3]);
            }
        }
        if (c < 14) { store_c(cur ^ 1); __syncthreads(); }
    }

#pragma unroll
    for (int ni = 0; ni < 8; ni++) {
        int n = n0 + (ni >> 2) * 64 + ty * 4 + (ni & 3);
        if (n >= G4) continue;
        float bn = bias[n];
        size_t base = ((size_t)t * G4 + n) * Bv + p0;
        float2 u0 = unpack2(acc2[ni][0]);
        float2 u1 = unpack2(acc2[ni][1]);
        float2 u2 = unpack2(acc2[ni][2]);
        float2 u3 = unpack2(acc2[ni][3]);
        float4 v0 = make_float4(u0.x + bn, u0.y + bn, u1.x + bn, u1.y + bn);
        float4 v1 = make_float4(u2.x + bn, u2.y + bn, u3.x + bn, u3.y + bn);
        __stcs((float4*)&g_xpre[base + tx * 4],      v0);
        __stcs((float4*)&g_xpre[base + tx * 4 + 64], v1);
    }
}

// ---------------------------------------------------------------------------
// Persistent LSTM recurrence — crossbar-dedup geometry:
// tile 64p x W j, 256 threads. W=16: TPJ=16, PPT=4 (2 j-cols per warp share
// h bytes -> 2 phases) ; W=8: TPJ=32, PPT=2.
// ---------------------------------------------------------------------------
__device__ __forceinline__ float sigmoidf_(float x) {
    return 1.f / (1.f + __expf(-x));
}
__device__ __forceinline__ float tanhf_(float x) {
    return 1.f - 2.f / (__expf(2.f * x) + 1.f);
}

__device__ __forceinline__ void grid_barrier(unsigned target) {
    __threadfence();
    __syncthreads();
    if (threadIdx.x == 0) {
        if (atomicAdd(&g_bar_count, 1u) == NBLK - 1) {
            g_bar_count = 0;
            __threadfence();
            atomicExch(&g_bar_sense, target);
        } else {
            while (*(volatile unsigned*)&g_bar_sense < target) __nanosleep(32);
        }
    }
    __syncthreads();
}

template<int W>
__device__ __forceinline__ void step_tile_full(
    float hs[2][30][64], const float4* __restrict__ ws4,
    const float* __restrict__ hin, float* __restrict__ hout,
    int t, int p0, int j0, int act)
{
    constexpr int TPJ = NTHR / W;        // 16 (W=16) or 32 (W=8)
    constexpr int PPT = 64 / TPJ;        // 4 or 2
    const int tid  = threadIdx.x;
    const int pidx = tid % TPJ;
    const int jc   = tid / TPJ;
    const int j    = j0 + jc;

    // stage 30k x 64p = 480 float4 per chunk over 256 threads (2 slots)
    float4 ph[2];
    auto load_c = [&](int k0) {
#pragma unroll
        for (int i = 0; i < 2; i++) {
            int f = i * NTHR + tid;
            if (f < 480)
                ph[i] = __ldcg((const float4*)&hin[(k0 + (f >> 4)) * Bv + p0
                                                   + ((f & 15) << 2)]);
        }
    };
    auto store_c = [&](int buf) {
#pragma unroll
        for (int i = 0; i < 2; i++) {
            int f = i * NTHR + tid;
            if (f < 480)
                *(float4*)&hs[buf][f >> 4][(f & 15) << 2] = ph[i];
        }
    };

    // packed accumulators per p: acc01 = (g0,g1), acc23 = (g2,g3)
    ull acc01[PPT], acc23[PPT];
#pragma unroll
    for (int p = 0; p < PPT; p++) { acc01[p] = 0ull; acc23[p] = 0ull; }

    load_c(0);
    store_c(0);
    __syncthreads();

#pragma unroll 1
    for (int c = 0; c < 10; c++) {
        const int cur = c & 1;
        if (c < 9) load_c((c + 1) * 30);
#pragma unroll
        for (int kk = 0; kk < 30; kk++) {
            const int k = c * 30 + kk;
            ulonglong2 wv = *(const ulonglong2*)&ws4[k * W + jc]; // (g0g1),(g2g3)
            if (PPT == 4) {
                float4 h4 = *(const float4*)&hs[cur][kk][pidx * 4];
                ull hh0 = pack_dup(h4.x);
                ull hh1 = pack_dup(h4.y);
                ull hh2 = pack_dup(h4.z);
                ull hh3 = pack_dup(h4.w);
                fma2(acc01[0], hh0, wv.x);
                fma2(acc23[0], hh0, wv.y);
                fma2(acc01[1], hh1, wv.x);
                fma2(acc23[1], hh1, wv.y);
                fma2(acc01[2], hh2, wv.x);
                fma2(acc23[2], hh2, wv.y);
                fma2(acc01[3], hh3, wv.x);
                fma2(acc23[3], hh3, wv.y);
            } else {
                float2 h2 = *(const float2*)&hs[cur][kk][pidx * 2];
                ull hh0 = pack_dup(h2.x);
                ull hh1 = pack_dup(h2.y);
                fma2(acc01[0], hh0, wv.x);
                fma2(acc23[0], hh0, wv.y);
                fma2(acc01[1], hh1, wv.x);
                fma2(acc23[1], hh1, wv.y);
            }
        }
        if (c < 9) { store_c(cur ^ 1); __syncthreads(); }
    }

    if (j < Hv) {
        const size_t tb = (size_t)t * G4;
        const int pb = p0 + pidx * PPT;
        const int hi = j * Bv + pb;

        if (pb + PPT <= act) {             // fully active: vector path
            float xp[4][PPT];
#pragma unroll
            for (int g = 0; g < 4; g++) {
                if (PPT == 4) {
                    float4 v = __ldcs((const float4*)&g_xpre[(tb + g * Hv + j) * Bv + pb]);
                    xp[g][0] = v.x; xp[g][1] = v.y; xp[g][2] = v.z; xp[g][3] = v.w;
                } else {
                    float2 v = __ldcs((const float2*)&g_xpre[(tb + g * Hv + j) * Bv + pb]);
                    xp[g][0] = v.x; xp[g][1] = v.y;
                }
            }
            float cold[PPT], hn[PPT], cn[PPT];
            if (PPT == 4) {
                float4 c4 = __ldcg((const float4*)&g_cT[hi]);
                cold[0] = c4.x; cold[1] = c4.y; cold[2] = c4.z; cold[3] = c4.w;
            } else {
                float2 c2 = __ldcg((const float2*)&g_cT[hi]);
                cold[0] = c2.x; cold[1] = c2.y;
            }
#pragma unroll
            for (int p = 0; p < PPT; p++) {
                float2 g01 = unpack2(acc01[p]);
                float2 g23 = unpack2(acc23[p]);
                float iv = sigmoidf_(g01.x + xp[0][p]);
                float fv = sigmoidf_(g01.y + xp[1][p]);
                float gv = tanhf_   (g23.x + xp[2][p]);
                float ov = sigmoidf_(g23.y + xp[3][p]);
                cn[p] = fv * cold[p] + iv * gv;
                hn[p] = ov * tanhf_(cn[p]);
            }
            if (PPT == 4) {
                __stcg((float4*)&hout[hi], make_float4(hn[0], hn[1], hn[2], hn[3]));
                __stcg((float4*)&g_cT[hi], make_float4(cn[0], cn[1], cn[2], cn[3]));
            } else {
                __stcg((float2*)&hout[hi], make_float2(hn[0], hn[1]));
                __stcg((float2*)&g_cT[hi], make_float2(cn[0], cn[1]));
            }
        } else {                            // straddle: masked scalar
#pragma unroll
            for (int p = 0; p < PPT; p++) {
                const int pp = pb + p;
                if (pp >= act) continue;
                float2 g01 = unpack2(acc01[p]);
                float2 g23 = unpack2(acc23[p]);
                float gi = g01.x + __ldcs(&g_xpre[(tb + 0 * Hv + j) * Bv + pp]);
                float gf = g01.y + __ldcs(&g_xpre[(tb + 1 * Hv + j) * Bv + pp]);
                float gg = g23.x + __ldcs(&g_xpre[(tb + 2 * Hv + j) * Bv + pp]);
                float go = g23.y + __ldcs(&g_xpre[(tb + 3 * Hv + j) * Bv + pp]);
                float iv = sigmoidf_(gi);
                float fv = sigmoidf_(gf);
                float gv = tanhf_(gg);
                float ov = sigmoidf_(go);
                float cold = __ldcg(&g_cT[hi + p]);
                float cnew = fv * cold + iv * gv;
                float hnew = ov * tanhf_(cnew);
                __stcg(&g_cT[hi + p], cnew);
                __stcg(&hout[hi + p], hnew);
            }
        }
    }
    __syncthreads();   // protect hs before next tile reuses it
}

__global__ __launch_bounds__(NTHR, 2) void lstm_kernel()
{
    extern __shared__ __align__(16) char smem_raw[];
    float4* ws4 = (float4*)smem_raw;                            // 76800 B
    float (*hs)[30][64] = (float(*)[30][64])(smem_raw + 76800); // 15360 B

    const int bid = blockIdx.x;
    const int tid = threadIdx.x;
    int wlast = 0;

#pragma unroll 1
    for (int t = 0; t < Tv; t++) {
        const int act = g_act[t];
        const int na  = (act + 63) >> 6;
        const float* hin  = g_hT[t & 1];
        float*       hout = g_hT[(t & 1) ^ 1];

        int w, njt, lw;
        if (na >= 8) { w = 16; njt = 19; lw = 4; }
        else         { w = 8;  njt = 38; lw = 3; }
        const int jt  = bid % njt;
        const int ptb = bid / njt;
        const int j0  = jt * w;

        if (w != wlast) {    // phase change (happens once): load Wh slice
            for (int idx = tid; idx < 300 * w; idx += NTHR) {
                int k   = idx >> lw;
                int jj  = idx & (w - 1);
                int col = j0 + jj;
                ws4[idx] = (col < Hv) ? g_whT[k * Hv + col]
                                      : make_float4(0.f, 0.f, 0.f, 0.f);
            }
            wlast = w;
            __syncthreads();
        }

        int stride;
        if (w == 16) stride = 15;                   // 285 = 19*15 exact
        else         stride = (jt < 19) ? 8 : 7;    // 285 = 7*38 + 19

        if (w == 16) {
            for (int pp = ptb; pp * 64 < act; pp += stride)
                step_tile_full<16>(hs, ws4, hin, hout, t, pp * 64, j0, act);
        } else {
            for (int pp = ptb; pp * 64 < act; pp += stride)
                step_tile_full<8>(hs, ws4, hin, hout, t, pp * 64, j0, act);
        }
        grid_barrier(t + 1);
    }
}

// ---------------------------------------------------------------------------
// Output: final h for batch b lives in buffer lens[b] & 1 (written at len-1).
// ---------------------------------------------------------------------------
__global__ void out_kernel(const int* __restrict__ lens,
                           const float* __restrict__ Wout,
                           const float* __restrict__ bout,
                           float* __restrict__ out)
{
    int gwarp = (blockIdx.x * blockDim.x + threadIdx.x) >> 5;
    int lane  = threadIdx.x & 31;
    if (gwarp >= Bv) return;

    const int p = g_rank[gwarp];
    const float* hbuf = g_hT[lens[gwarp] & 1];
    float s0 = 0.f, s1 = 0.f, s2 = 0.f;
    for (int jj = lane; jj < Hv; jj += 32) {
        float hv = hbuf[jj * Bv + p];
        s0 = fmaf(hv, Wout[jj * 3 + 0], s0);
        s1 = fmaf(hv, Wout[jj * 3 + 1], s1);
        s2 = fmaf(hv, Wout[jj * 3 + 2], s2);
    }
#pragma unroll
    for (int off = 16; off > 0; off >>= 1) {
        s0 += __shfl_down_sync(0xffffffffu, s0, off);
        s1 += __shfl_down_sync(0xffffffffu, s1, off);
        s2 += __shfl_down_sync(0xffffffffu, s2, off);
    }
    if (lane == 0) {
        out[gwarp * 3 + 0] = s0 + bout[0];
        out[gwarp * 3 + 1] = s1 + bout[1];
        out[gwarp * 3 + 2] = s2 + bout[2];
    }
}

// ---------------------------------------------------------------------------
extern "C" void kernel_launch(void* const* d_in, const int* in_sizes, int n_in,
                              void* d_out, int out_size)
{
    const int*   sent = (const int*)  d_in[0];
    const int*   lens = (const int*)  d_in[1];
    const float* emb  = (const float*)d_in[2];
    const float* Wx   = (const float*)d_in[3];
    const float* Wh   = (const float*)d_in[4];
    const float* bias = (const float*)d_in[5];
    const float* Wout = (const float*)d_in[6];
    const float* bout = (const float*)d_in[7];
    float* out = (float*)d_out;

    cudaFuncSetAttribute(lstm_kernel,
                         cudaFuncAttributeMaxDynamicSharedMemorySize, LSTM_SMEM);

    init_kernel<<<1, 1024>>>(lens);
    zero_kernel<<<(Hv * Bv + 255) / 256, 256>>>();
    trans_kernel<<<(Hv * Hv + 255) / 256, 256>>>(Wh);

    dim3 pg(Bv / 128, (G4 + 127) / 128, Tv);   // 8 x 10 x 80
    pre_kernel<<<pg, 256>>>(sent, emb, Wx, bias);

    // one persistent launch for all 80 timesteps
    lstm_kernel<<<NBLK, NTHR, LSTM_SMEM>>>();

    out_kernel<<<(Bv * 32 + 127) / 128, 128>>>(lens, Wout, bout, out);
}